// round 7
// baseline (speedup 1.0000x reference)
#include <cuda_runtime.h>

// 4-D multilinear interpolation on an 8x8x8x8 lattice.
// coordinates: [32768, 4] float32 in [0,1]
// mesh_pred:   [32768, 4096] float32 (each point has its own lattice row)
// out:         [32768] float32
//
// Strides (row-major over mesh dims [8,8,8,8]): dim0=512, dim1=64, dim2=8, dim3=1.
//
// Geometry: 4 lanes per point (lane q owns (d0,d1) = (q>>1, q&1)), and each
// thread processes TWO points (p and p+16384) with all gather loads batched
// before any consumption, to maximize per-warp memory-level parallelism.
// Per (thread,point): two 16B-aligned float4 loads cover the dim3 pair
// {i3,i3+1} for d2=i2 and i2+1 (offset o=(i3>=4)?4:0), plus a predicated
// scalar fixup only when i3==3. Lane partials reduce via 2 butterfly shuffles.

#define BATCH  32768
#define VOLUME 4096
#define HALF   16384

struct PointWork {
    float4 A, B;       // pair regions for d2 = i2, i2+1
    float  a4, b4;     // fixup elements (only valid when l==3)
    int    l;          // local pair index within the aligned quad
    float  f0, f1, f2, f3;
};

__device__ __forceinline__ void addr_phase(const float4& c4, int q,
                                           const float* __restrict__ row_base,
                                           const float*& pA, const float*& pB,
                                           int& l, float& f0, float& f1,
                                           float& f2, float& f3)
{
    float c0 = c4.x * 7.0f, c1 = c4.y * 7.0f, c2 = c4.z * 7.0f, c3 = c4.w * 7.0f;
    int i0 = min(max((int)c0, 0), 6);
    int i1 = min(max((int)c1, 0), 6);
    int i2 = min(max((int)c2, 0), 6);
    int i3 = min(max((int)c3, 0), 6);
    f0 = c0 - (float)i0; f1 = c1 - (float)i1;
    f2 = c2 - (float)i2; f3 = c3 - (float)i3;

    int s0 = i0 * 512 + i1 * 64 + i2 * 8
           + ((q >> 1) ? 512 : 0) + ((q & 1) ? 64 : 0);
    int o = (i3 >= 4) ? 4 : 0;
    l = i3 - o;
    pA = row_base + s0 + o;
    pB = row_base + s0 + 8 + o;
}

__device__ __forceinline__ float finish(const PointWork& w, int q)
{
    int l = w.l;
    float v0 = (l == 0) ? w.A.x : (l == 1) ? w.A.y : (l == 2) ? w.A.z : w.A.w;
    float v1 = (l == 0) ? w.A.y : (l == 1) ? w.A.z : (l == 2) ? w.A.w : w.a4;
    float w0 = (l == 0) ? w.B.x : (l == 1) ? w.B.y : (l == 2) ? w.B.z : w.B.w;
    float w1 = (l == 0) ? w.B.y : (l == 1) ? w.B.z : (l == 2) ? w.B.w : w.b4;

    float u0 = fmaf(w.f3, v1 - v0, v0);
    float u1 = fmaf(w.f3, w1 - w0, w0);
    float t  = fmaf(w.f2, u1 - u0, u0);

    float wq = ((q >> 1) ? w.f0 : 1.0f - w.f0) * ((q & 1) ? w.f1 : 1.0f - w.f1);
    return t * wq;
}

__global__ __launch_bounds__(256, 4)
void HL_41996190220467_kernel(const float4* __restrict__ coords,
                              const float* __restrict__ mesh,
                              float* __restrict__ out)
{
    int t  = blockIdx.x * blockDim.x + threadIdx.x;
    int pi = t >> 2;          // 0 .. 16383
    int q  = t & 3;           // (d0,d1) octant-pair

    int p0 = pi;
    int p1 = pi + HALF;

    // Both coord loads issued back-to-back (independent).
    float4 c4_0 = coords[p0];
    float4 c4_1 = coords[p1];

    PointWork w0, w1;
    const float *pA0, *pB0, *pA1, *pB1;
    addr_phase(c4_0, q, mesh + (size_t)p0 * VOLUME, pA0, pB0,
               w0.l, w0.f0, w0.f1, w0.f2, w0.f3);
    addr_phase(c4_1, q, mesh + (size_t)p1 * VOLUME, pA1, pB1,
               w1.l, w1.f0, w1.f1, w1.f2, w1.f3);

    // All four gather loads in flight before any consumption.
    w0.A = *reinterpret_cast<const float4*>(pA0);
    w0.B = *reinterpret_cast<const float4*>(pB0);
    w1.A = *reinterpret_cast<const float4*>(pA1);
    w1.B = *reinterpret_cast<const float4*>(pB1);

    // Predicated fixups (needed only when l==3, i.e. i3==3, o==0).
    bool fx0 = (w0.l == 3), fx1 = (w1.l == 3);
    w0.a4 = fx0 ? __ldg(pA0 + 4) : 0.0f;
    w0.b4 = fx0 ? __ldg(pB0 + 4) : 0.0f;
    w1.a4 = fx1 ? __ldg(pA1 + 4) : 0.0f;
    w1.b4 = fx1 ? __ldg(pB1 + 4) : 0.0f;

    float r0 = finish(w0, q);
    float r1 = finish(w1, q);

    // Reduce both points across the 4 lanes (independent shuffle chains).
    r0 += __shfl_xor_sync(0xffffffffu, r0, 1);
    r1 += __shfl_xor_sync(0xffffffffu, r1, 1);
    r0 += __shfl_xor_sync(0xffffffffu, r0, 2);
    r1 += __shfl_xor_sync(0xffffffffu, r1, 2);

    if (q == 0) {
        out[p0] = r0;
        out[p1] = r1;
    }
}

extern "C" void kernel_launch(void* const* d_in, const int* in_sizes, int n_in,
                              void* d_out, int out_size)
{
    const float4* coords = (const float4*)d_in[0];   // [32768, 4]
    const float*  mesh   = (const float*)d_in[1];    // [32768, 4096]
    float* out = (float*)d_out;                      // [32768]
    (void)in_sizes; (void)n_in; (void)out_size;

    // 16384 point-pairs * 4 lanes = 65536 threads = 256 CTAs of 256
    HL_41996190220467_kernel<<<(BATCH / 2 * 4) / 256, 256>>>(coords, mesh, out);
}

// round 8
// speedup vs baseline: 1.0385x; 1.0385x over previous
#include <cuda_runtime.h>

// 4-D multilinear interpolation on an 8x8x8x8 lattice — 8 lanes per point.
// coordinates: [32768, 4] float32 in [0,1]
// mesh_pred:   [32768, 4096] float32 (each point has its own lattice row)
// out:         [32768] float32
//
// Strides (row-major over mesh dims [8,8,8,8]): dim0=512, dim1=64, dim2=8, dim3=1.
//
// Lane q = tid&7 owns the corner octant (d0,d1,d2) = (q>>2, (q>>1)&1, q&1).
// Its 8-float dim3 segment is 32B-aligned; the needed pair {i3, i3+1} sits in
// one 16B-aligned float4 at offset o=(i3>=4)?4:0, except i3==3 which takes a
// predicated scalar fixup. Each lane: ONE vector load, one dim3 lerp, weight
// multiply, then 3 butterfly shuffles sum the 8 octants.

#define BATCH  32768
#define VOLUME 4096

__global__ __launch_bounds__(256, 8)
void HL_41996190220467_kernel(const float4* __restrict__ coords,
                              const float* __restrict__ mesh,
                              float* __restrict__ out)
{
    int t = blockIdx.x * blockDim.x + threadIdx.x;
    int p = t >> 3;          // point index
    int q = t & 7;           // octant: d0=q>>2, d1=(q>>1)&1, d2=q&1

    float4 c4 = coords[p];   // 8 lanes broadcast-load the same 16B

    float c0 = c4.x * 7.0f;
    float c1 = c4.y * 7.0f;
    float c2 = c4.z * 7.0f;
    float c3 = c4.w * 7.0f;

    int i0 = min(max((int)c0, 0), 6);
    int i1 = min(max((int)c1, 0), 6);
    int i2 = min(max((int)c2, 0), 6);
    int i3 = min(max((int)c3, 0), 6);

    float f0 = c0 - (float)i0;
    float f1 = c1 - (float)i1;
    float f2 = c2 - (float)i2;
    float f3 = c3 - (float)i3;

    const float* __restrict__ row = mesh + (size_t)p * VOLUME;

    // this lane's segment base (multiple of 8 floats -> 32B aligned)
    int s = i0 * 512 + i1 * 64 + i2 * 8
          + ((q >> 2) ? 512 : 0)
          + ((q >> 1) & 1 ? 64 : 0)
          + ((q & 1) ? 8 : 0);

    int o = (i3 >= 4) ? 4 : 0;   // aligned quad containing the pair
    int l = i3 - o;              // 0..3 (3 only when i3==3)

    float4 A = *reinterpret_cast<const float4*>(row + s + o);

    // fixup: element at local index 4, needed only when i3==3 (then o==0)
    float a4 = (l == 3) ? __ldg(row + s + 4) : 0.0f;

    float v0 = (l == 0) ? A.x : (l == 1) ? A.y : (l == 2) ? A.z : A.w;
    float v1 = (l == 0) ? A.y : (l == 1) ? A.z : (l == 2) ? A.w : a4;

    // dim3 lerp, then this octant's (d0,d1,d2) weight
    float u  = fmaf(f3, v1 - v0, v0);
    float wq = ((q >> 2) ? f0 : 1.0f - f0)
             * (((q >> 1) & 1) ? f1 : 1.0f - f1)
             * ((q & 1) ? f2 : 1.0f - f2);
    float r = u * wq;

    // sum the 8 octants of this point
    r += __shfl_xor_sync(0xffffffffu, r, 1);
    r += __shfl_xor_sync(0xffffffffu, r, 2);
    r += __shfl_xor_sync(0xffffffffu, r, 4);

    if (q == 0) out[p] = r;
}

extern "C" void kernel_launch(void* const* d_in, const int* in_sizes, int n_in,
                              void* d_out, int out_size)
{
    const float4* coords = (const float4*)d_in[0];   // [32768, 4]
    const float*  mesh   = (const float*)d_in[1];    // [32768, 4096]
    float* out = (float*)d_out;                      // [32768]
    (void)in_sizes; (void)n_in; (void)out_size;

    // 32768 points * 8 lanes = 262144 threads = 1024 CTAs of 256
    HL_41996190220467_kernel<<<(BATCH * 8) / 256, 256>>>(coords, mesh, out);
}